// round 6
// baseline (speedup 1.0000x reference)
#include <cuda_runtime.h>
#include <cstdint>
#include <math.h>

// ---------------------------------------------------------------------------
// Problem dims
// ---------------------------------------------------------------------------
#define T_STEPS 128
#define B_SZ    512
#define IN_SZ   784
#define H_SZ    2048
#define OUT_SZ  10
#define MB      (T_STEPS * B_SZ)          // 65536 GEMM rows
#define BH      (B_SZ * H_SZ)             // 1048576 neurons

#define KT      784                       // K (784 % 16 == 0)
#define KP      1568                      // packed row stride: [hi(784) | lo(784)]

// GEMM tiling
#define BM_T    128
#define BN_T    128
#define BK_T    16                        // K elements per stage
#define NSTG    49                        // 784 / 16
#define ROWPAD  20                        // floats per smem row (80 B, conflict-free)
#define REGION  (128 * ROWPAD * 4)        // 10240 B: one of {Ahi,Alo,Bhi,Blo}
#define STAGEB  (4 * REGION)              // 40960 B per stage
#define SMEMB   (4 * STAGEB)              // 163840 B total (4 stages)

// Scratch (device globals — no runtime allocation allowed)
__device__ float g_cur[(size_t)MB * H_SZ];     // 512 MB
__device__ float g_A[(size_t)MB * KP];         // 411 MB packed [hi|lo] X
__device__ float g_B[(size_t)H_SZ * KP];       // 13 MB packed [hi|lo] W1
__device__ float g_S[(size_t)B_SZ * H_SZ];     // weighted spike sums
__device__ float g_coef[T_STEPS];

// ---------------------------------------------------------------------------
// PTX helpers (arch-agnostic only: cp.async + mma.sync)
// ---------------------------------------------------------------------------
__device__ __forceinline__ uint32_t smem_u32(const void* p) {
    uint32_t a;
    asm("{ .reg .u64 t; cvta.to.shared.u64 t, %1; cvt.u32.u64 %0, t; }"
        : "=r"(a) : "l"(p));
    return a;
}
#define CP16(dst, src) \
    asm volatile("cp.async.cg.shared.global [%0], [%1], 16;" :: "r"(dst), "l"(src) : "memory")
#define CP_COMMIT() asm volatile("cp.async.commit_group;" ::: "memory")
#define CP_WAIT1()  asm volatile("cp.async.wait_group 1;" ::: "memory")

#define LDS32(reg, addr) \
    asm volatile("ld.shared.b32 %0, [%1];" : "=r"(reg) : "r"(addr))

// D += A*B  (m16n8k8, tf32 inputs as raw b32, fp32 accumulate)
#define MMA_TF32(c, a, b)                                                      \
    asm volatile(                                                              \
        "mma.sync.aligned.m16n8k8.row.col.f32.tf32.tf32.f32 "                  \
        "{%0,%1,%2,%3}, {%4,%5,%6,%7}, {%8,%9}, {%0,%1,%2,%3};"                \
        : "+f"((c)[0]), "+f"((c)[1]), "+f"((c)[2]), "+f"((c)[3])               \
        : "r"((a)[0]), "r"((a)[1]), "r"((a)[2]), "r"((a)[3]),                  \
          "r"((b)[0]), "r"((b)[1]))

// round-to-nearest onto the tf32 (10-bit explicit mantissa) grid
__device__ __forceinline__ float tf32_rn(float v) {
    uint32_t u = __float_as_uint(v);
    u = (u + 0x1000u) & 0xFFFFE000u;
    return __uint_as_float(u);
}

// ---------------------------------------------------------------------------
// Kernel 0: readout coefficients  c_t = 0.9^(127-t) - 0.8^(127-t)
// ---------------------------------------------------------------------------
__global__ void coef_kernel() {
    int t = threadIdx.x;
    if (t < T_STEPS) {
        float m = (float)(T_STEPS - 1 - t);
        g_coef[t] = powf(0.9f, m) - powf(0.8f, m);
    }
}

// ---------------------------------------------------------------------------
// Pack kernels: split fp32 -> (hi, lo) tf32 pairs, layout [hi(784) | lo(784)]
// ---------------------------------------------------------------------------
__global__ __launch_bounds__(256)
void packA_kernel(const float* __restrict__ x) {
    size_t m = blockIdx.x;
    const float* src = x + m * IN_SZ;
    float* dst = g_A + m * KP;
    for (int k = threadIdx.x; k < KT; k += 256) {
        float v = src[k];
        float hi = tf32_rn(v);
        dst[k] = hi;
        dst[KT + k] = tf32_rn(v - hi);
    }
}
__global__ __launch_bounds__(256)
void packB_kernel(const float* __restrict__ w) {
    size_t n = blockIdx.x;
    const float* src = w + n * IN_SZ;
    float* dst = g_B + n * KP;
    for (int k = threadIdx.x; k < KT; k += 256) {
        float v = src[k];
        float hi = tf32_rn(v);
        dst[k] = hi;
        dst[KT + k] = tf32_rn(v - hi);
    }
}

// ---------------------------------------------------------------------------
// GEMM: CUR[65536,2048] = X @ W1^T with tf32x3 emulation on mma.sync.
// 128x128 CTA tile, 8 warps (4x2) of 32x64 warp tiles, BK=16, 4-stage cp.async.
// NEW: register-level fragment double-buffering at half-stage (ks) granularity,
// so LDS (smem crossbar) overlaps tensor-pipe work instead of phase-aligning.
// Per-accumulator MMA order (hh,hl,lh per ks, ks ascending, stages ascending)
// is IDENTICAL to the previous passing kernel -> bit-identical results.
// ---------------------------------------------------------------------------
__global__ __launch_bounds__(256, 1)
void mma_kernel() {
    extern __shared__ __align__(16) char smem[];
    const uint32_t sbase = smem_u32(smem);

    const int tid  = threadIdx.x;
    const int wid  = tid >> 5;
    const int lane = tid & 31;
    const int lq   = lane >> 2;           // 0..7
    const int lr   = lane & 3;            // 0..3
    const int warp_m = wid & 3;           // 4 strips of 32 rows
    const int warp_n = wid >> 2;          // 2 strips of 64 cols

    const int n0 = blockIdx.x * BN_T;     // x fastest -> A-tile L2 reuse
    const int m0 = blockIdx.y * BM_T;

    // ---- producer mapping: 8 x 16B cp.async per thread per stage ----
    const int prow = tid >> 1;            // 0..127
    const int pcol = (tid & 1) * 8;       // float offset 0 or 8 within 16-chunk
    const float* ga = g_A + (size_t)(m0 + prow) * KP;
    const float* gb = g_B + (size_t)(n0 + prow) * KP;
    const uint32_t prowoff = (uint32_t)prow * 80u + (uint32_t)(tid & 1) * 32u;

    float acc[2][8][4];
#pragma unroll
    for (int mi = 0; mi < 2; mi++)
#pragma unroll
        for (int ni = 0; ni < 8; ni++)
#pragma unroll
            for (int q = 0; q < 4; q++) acc[mi][ni][q] = 0.0f;

    // fragment base byte-offsets within a region
    const uint32_t a_off0 = (uint32_t)(warp_m * 32 + lq) * 80u + (uint32_t)lr * 4u;
    const uint32_t b_off0 = (uint32_t)(warp_n * 64 + lq) * 80u + (uint32_t)lr * 4u;

    // register fragment double-buffers (P = ks parity)
    uint32_t fa_h[2][2][4], fa_l[2][2][4], fb_h[2][8][2], fb_l[2][8][2];

#define LOAD_STAGE(buf, kc) do {                                               \
    uint32_t st = sbase + (uint32_t)(buf) * STAGEB;                            \
    const float* ga_h = ga + (kc) + pcol;                                      \
    const float* gb_h = gb + (kc) + pcol;                                      \
    _Pragma("unroll")                                                          \
    for (int j = 0; j < 2; j++) {                                              \
        uint32_t d = prowoff + (uint32_t)j * 16u;                              \
        CP16(st + 0 * REGION + d, ga_h + j * 4);                               \
        CP16(st + 1 * REGION + d, ga_h + KT + j * 4);                          \
        CP16(st + 2 * REGION + d, gb_h + j * 4);                               \
        CP16(st + 3 * REGION + d, gb_h + KT + j * 4);                          \
    } } while (0)

// Load one ks sub-step's fragments (48 LDS32) into register buffer P.
// ST = smem stage base, KO = ks byte offset (0 or 32).
#define PRELOAD(P, ST, KO) do {                                                \
    const uint32_t _sah = (ST) + 0 * REGION + a_off0 + (KO);                   \
    const uint32_t _sal = (ST) + 1 * REGION + a_off0 + (KO);                   \
    const uint32_t _sbh = (ST) + 2 * REGION + b_off0 + (KO);                   \
    const uint32_t _sbl = (ST) + 3 * REGION + b_off0 + (KO);                   \
    _Pragma("unroll")                                                          \
    for (int mi = 0; mi < 2; mi++) {                                           \
        uint32_t base = (uint32_t)mi * (16u * 80u);                            \
        LDS32(fa_h[P][mi][0], _sah + base);                                    \
        LDS32(fa_h[P][mi][1], _sah + base + 640u);                             \
        LDS32(fa_h[P][mi][2], _sah + base + 16u);                              \
        LDS32(fa_h[P][mi][3], _sah + base + 656u);                             \
        LDS32(fa_l[P][mi][0], _sal + base);                                    \
        LDS32(fa_l[P][mi][1], _sal + base + 640u);                             \
        LDS32(fa_l[P][mi][2], _sal + base + 16u);                              \
        LDS32(fa_l[P][mi][3], _sal + base + 656u);                             \
    }                                                                          \
    _Pragma("unroll")                                                          \
    for (int ni = 0; ni < 8; ni++) {                                           \
        uint32_t base = (uint32_t)ni * (8u * 80u);                             \
        LDS32(fb_h[P][ni][0], _sbh + base);                                    \
        LDS32(fb_h[P][ni][1], _sbh + base + 16u);                              \
        LDS32(fb_l[P][ni][0], _sbl + base);                                    \
        LDS32(fb_l[P][ni][1], _sbl + base + 16u);                              \
    } } while (0)

// All 48 MMAs for buffer P; term-outer; per-acc order hh -> hl -> lh.
#define MMA_ALL(P) do {                                                        \
    _Pragma("unroll")                                                          \
    for (int mi = 0; mi < 2; mi++)                                             \
        _Pragma("unroll")                                                      \
        for (int ni = 0; ni < 8; ni++)                                         \
            MMA_TF32(acc[mi][ni], fa_h[P][mi], fb_h[P][ni]);                   \
    _Pragma("unroll")                                                          \
    for (int mi = 0; mi < 2; mi++)                                             \
        _Pragma("unroll")                                                      \
        for (int ni = 0; ni < 8; ni++)                                         \
            MMA_TF32(acc[mi][ni], fa_h[P][mi], fb_l[P][ni]);                   \
    _Pragma("unroll")                                                          \
    for (int mi = 0; mi < 2; mi++)                                             \
        _Pragma("unroll")                                                      \
        for (int ni = 0; ni < 8; ni++)                                         \
            MMA_TF32(acc[mi][ni], fa_l[P][mi], fb_h[P][ni]);                   \
    } while (0)

    // prologue: stages 0..2 committed (3 groups outstanding)
    LOAD_STAGE(0, 0);  CP_COMMIT();
    LOAD_STAGE(1, 16); CP_COMMIT();
    LOAD_STAGE(2, 32); CP_COMMIT();

    for (int k = 0; k < NSTG; k++) {
        CP_WAIT1();                 // stages k AND k+1 resident
        __syncthreads();            // visibility + stage k-1 consumption done

        // prefetch stage k+3 into buffer (k+3)&3 == (k-1)&3 (free post-barrier)
        if (k + 3 < NSTG) LOAD_STAGE((k + 3) & 3, (k + 3) * BK_T);
        CP_COMMIT();                // always commit (empty ok) to keep count

        const uint32_t st  = sbase + (uint32_t)(k & 3) * STAGEB;
        const uint32_t stn = sbase + (uint32_t)((k + 1) & 3) * STAGEB;

        if (k == 0) PRELOAD(0, st, 0u);      // bootstrap (once)
        PRELOAD(1, st, 32u);                 // ks=1 frags (hides under MMA 0)
        MMA_ALL(0);                          // compute ks=0
        if (k + 1 < NSTG) PRELOAD(0, stn, 0u); // next stage ks=0 (hides under MMA 1)
        MMA_ALL(1);                          // compute ks=1
    }

    // epilogue: write C
#pragma unroll
    for (int mi = 0; mi < 2; mi++) {
        const int gm = m0 + warp_m * 32 + mi * 16 + lq;
        float* r0 = g_cur + (size_t)gm * H_SZ + n0 + warp_n * 64 + lr * 2;
        float* r1 = r0 + 8 * H_SZ;
#pragma unroll
        for (int ni = 0; ni < 8; ni++) {
            *(float2*)(r0 + ni * 8) = make_float2(acc[mi][ni][0], acc[mi][ni][1]);
            *(float2*)(r1 + ni * 8) = make_float2(acc[mi][ni][2], acc[mi][ni][3]);
        }
    }
#undef LOAD_STAGE
#undef PRELOAD
#undef MMA_ALL
}

// ---------------------------------------------------------------------------
// LIF scan: S = sum_t c_t * z_t   (per-neuron, state in registers)
// ---------------------------------------------------------------------------
__global__ __launch_bounds__(256)
void scan_kernel() {
    const int gid = blockIdx.x * blockDim.x + threadIdx.x;
    const float4* cur4 = (const float4*)g_cur;

    float v0 = 0.f, v1 = 0.f, v2 = 0.f, v3 = 0.f;
    float i0 = 0.f, i1 = 0.f, i2 = 0.f, i3 = 0.f;
    float s0 = 0.f, s1 = 0.f, s2 = 0.f, s3 = 0.f;

#pragma unroll 4
    for (int t = 0; t < T_STEPS; t++) {
        float4 c = __ldg(&cur4[(size_t)t * (BH / 4) + gid]);
        float coef = g_coef[t];
        float vd, id;
        vd = v0 + 0.1f * ((0.0f - v0) + i0); id = 0.8f * i0;
        if ((vd - 0.25f) > 0.0f) { v0 = 0.0f; s0 += coef; } else { v0 = vd; }
        i0 = id + c.x;
        vd = v1 + 0.1f * ((0.0f - v1) + i1); id = 0.8f * i1;
        if ((vd - 0.25f) > 0.0f) { v1 = 0.0f; s1 += coef; } else { v1 = vd; }
        i1 = id + c.y;
        vd = v2 + 0.1f * ((0.0f - v2) + i2); id = 0.8f * i2;
        if ((vd - 0.25f) > 0.0f) { v2 = 0.0f; s2 += coef; } else { v2 = vd; }
        i2 = id + c.z;
        vd = v3 + 0.1f * ((0.0f - v3) + i3); id = 0.8f * i3;
        if ((vd - 0.25f) > 0.0f) { v3 = 0.0f; s3 += coef; } else { v3 = vd; }
        i3 = id + c.w;
    }
    ((float4*)g_S)[gid] = make_float4(s0, s1, s2, s3);
}

// ---------------------------------------------------------------------------
// Readout: vo = S @ Wout^T
// ---------------------------------------------------------------------------
__global__ __launch_bounds__(256)
void readout_kernel(const float* __restrict__ Wout, float* __restrict__ out) {
    const int b = blockIdx.x;
    const int tid = threadIdx.x;
    float acc[OUT_SZ];
#pragma unroll
    for (int o = 0; o < OUT_SZ; o++) acc[o] = 0.0f;

    const float* srow = g_S + (size_t)b * H_SZ;
    for (int h = tid; h < H_SZ; h += 256) {
        float sv = srow[h];
#pragma unroll
        for (int o = 0; o < OUT_SZ; o++)
            acc[o] = fmaf(sv, __ldg(&Wout[o * H_SZ + h]), acc[o]);
    }
    __shared__ float red[OUT_SZ][8];
    const int lane = tid & 31, warp = tid >> 5;
#pragma unroll
    for (int o = 0; o < OUT_SZ; o++) {
        float v = acc[o];
#pragma unroll
        for (int off = 16; off; off >>= 1) v += __shfl_down_sync(0xffffffffu, v, off);
        if (lane == 0) red[o][warp] = v;
    }
    __syncthreads();
    if (tid < OUT_SZ) {
        float v = 0.0f;
#pragma unroll
        for (int w = 0; w < 8; w++) v += red[tid][w];
        out[b * OUT_SZ + tid] = v;
    }
}

// ---------------------------------------------------------------------------
extern "C" void kernel_launch(void* const* d_in, const int* in_sizes, int n_in,
                              void* d_out, int out_size) {
    const float* x    = (const float*)d_in[0];   // [128,512,784]
    const float* W1   = (const float*)d_in[1];   // [2048,784]
    const float* Wout = (const float*)d_in[2];   // [10,2048]
    float* out = (float*)d_out;                  // [512,10]

    coef_kernel<<<1, 128>>>();
    packA_kernel<<<MB, 256>>>(x);
    packB_kernel<<<H_SZ, 256>>>(W1);

    cudaFuncSetAttribute(mma_kernel, cudaFuncAttributeMaxDynamicSharedMemorySize, SMEMB);
    dim3 grid(H_SZ / BN_T, MB / BM_T);   // (16, 512), x fastest
    mma_kernel<<<grid, 256, SMEMB>>>();

    scan_kernel<<<BH / 4 / 256, 256>>>();
    readout_kernel<<<B_SZ, 256>>>(Wout, out);
}

// round 7
// speedup vs baseline: 1.3298x; 1.3298x over previous
#include <cuda_runtime.h>
#include <cuda_fp16.h>
#include <cstdint>
#include <math.h>

// ---------------------------------------------------------------------------
// Problem dims
// ---------------------------------------------------------------------------
#define T_STEPS 128
#define B_SZ    512
#define IN_SZ   784
#define H_SZ    2048
#define OUT_SZ  10
#define MB      (T_STEPS * B_SZ)          // 65536 GEMM rows
#define BH      (B_SZ * H_SZ)             // 1048576 neurons

#define KT      784                       // K elements
#define KAP     1568                      // packed row stride in halfs: [hi|lo]

// GEMM tiling
#define BM_T    128
#define BN_T    128
#define BK_T    16                        // K per stage = one m16n8k16 MMA
#define NSTG    49                        // 784 / 16
#define RB      48                        // smem row bytes (32B data + 16B pad)
#define REGION  (128 * RB)                // 6144 B: one of {Ahi,Alo,Bhi,Blo}
#define STAGEB  (4 * REGION)              // 24576 B per stage
#define SMEMB   (4 * STAGEB)              // 98304 B total (4 stages)

// Scratch (device globals — no runtime allocation allowed)
__device__ float  g_cur[(size_t)MB * H_SZ];    // 512 MB
__device__ __half g_A[(size_t)MB * KAP];       // 205 MB packed [hi|lo] X (fp16)
__device__ __half g_B[(size_t)H_SZ * KAP];     // 6.4 MB packed [hi|lo] W1
__device__ float  g_S[(size_t)B_SZ * H_SZ];    // weighted spike sums
__device__ float  g_coef[T_STEPS];

// ---------------------------------------------------------------------------
// PTX helpers (arch-agnostic only: cp.async + mma.sync)
// ---------------------------------------------------------------------------
__device__ __forceinline__ uint32_t smem_u32(const void* p) {
    uint32_t a;
    asm("{ .reg .u64 t; cvta.to.shared.u64 t, %1; cvt.u32.u64 %0, t; }"
        : "=r"(a) : "l"(p));
    return a;
}
#define CP16(dst, src) \
    asm volatile("cp.async.cg.shared.global [%0], [%1], 16;" :: "r"(dst), "l"(src) : "memory")
#define CP_COMMIT() asm volatile("cp.async.commit_group;" ::: "memory")
#define CP_WAIT2()  asm volatile("cp.async.wait_group 2;" ::: "memory")

#define LDS32(reg, addr) \
    asm volatile("ld.shared.b32 %0, [%1];" : "=r"(reg) : "r"(addr))

// D += A*B  (m16n8k16, fp16 inputs packed f16x2 in b32 regs, fp32 accumulate)
#define MMA_F16(c, a, b)                                                       \
    asm volatile(                                                              \
        "mma.sync.aligned.m16n8k16.row.col.f32.f16.f16.f32 "                   \
        "{%0,%1,%2,%3}, {%4,%5,%6,%7}, {%8,%9}, {%0,%1,%2,%3};"                \
        : "+f"((c)[0]), "+f"((c)[1]), "+f"((c)[2]), "+f"((c)[3])               \
        : "r"((a)[0]), "r"((a)[1]), "r"((a)[2]), "r"((a)[3]),                  \
          "r"((b)[0]), "r"((b)[1]))

// ---------------------------------------------------------------------------
// Kernel 0: readout coefficients  c_t = 0.9^(127-t) - 0.8^(127-t)
// ---------------------------------------------------------------------------
__global__ void coef_kernel() {
    int t = threadIdx.x;
    if (t < T_STEPS) {
        float m = (float)(T_STEPS - 1 - t);
        g_coef[t] = powf(0.9f, m) - powf(0.8f, m);
    }
}

// ---------------------------------------------------------------------------
// Pack kernels: split fp32 -> (hi, lo) fp16 pairs (11-bit limbs, same info
// content as the tf32 split), layout [hi(784) | lo(784)] halfs.
// ---------------------------------------------------------------------------
__global__ __launch_bounds__(256)
void packA_kernel(const float* __restrict__ x) {
    size_t m = blockIdx.x;
    const float* src = x + m * IN_SZ;
    __half* dst = g_A + m * KAP;
    for (int k = threadIdx.x; k < KT; k += 256) {
        float v = src[k];
        __half h = __float2half_rn(v);
        dst[k] = h;
        dst[KT + k] = __float2half_rn(v - __half2float(h));
    }
}
__global__ __launch_bounds__(256)
void packB_kernel(const float* __restrict__ w) {
    size_t n = blockIdx.x;
    const float* src = w + n * IN_SZ;
    __half* dst = g_B + n * KAP;
    for (int k = threadIdx.x; k < KT; k += 256) {
        float v = src[k];
        __half h = __float2half_rn(v);
        dst[k] = h;
        dst[KT + k] = __float2half_rn(v - __half2float(h));
    }
}

// ---------------------------------------------------------------------------
// GEMM: CUR[65536,2048] = X @ W1^T with fp16x3 emulation on mma.sync m16n8k16.
// 128x128 CTA tile, 8 warps (4x2) of 32x64 warp tiles, BK=16, 4-stage cp.async.
// Per stage per warp: 48 LDS32 + 48 HMMA (16 accs x {hh, hl, lh}).
// smem row stride 48B -> all warp-wide LDS32 patterns bank-conflict-free.
// ---------------------------------------------------------------------------
__global__ __launch_bounds__(256, 1)
void mma_kernel() {
    extern __shared__ __align__(16) char smem[];
    const uint32_t sbase = smem_u32(smem);

    const int tid  = threadIdx.x;
    const int wid  = tid >> 5;
    const int lane = tid & 31;
    const int lq   = lane >> 2;           // 0..7  (group)
    const int lr   = lane & 3;            // 0..3  (thread-in-group)
    const int warp_m = wid & 3;           // 4 strips of 32 rows
    const int warp_n = wid >> 2;          // 2 strips of 64 cols

    const int n0 = blockIdx.x * BN_T;     // x fastest -> A-tile L2 reuse
    const int m0 = blockIdx.y * BM_T;

    // ---- producer mapping: 4 x 16B cp.async per thread per stage ----
    const int prow = tid >> 1;            // 0..127
    const int pch  = (tid & 1) * 8;       // half offset 0 or 8 within 32B row
    const __half* ga = g_A + (size_t)(m0 + prow) * KAP;
    const __half* gb = g_B + (size_t)(n0 + prow) * KAP;
    const uint32_t prowoff = (uint32_t)prow * RB + (uint32_t)(tid & 1) * 16u;

    float acc[2][8][4];
#pragma unroll
    for (int mi = 0; mi < 2; mi++)
#pragma unroll
        for (int ni = 0; ni < 8; ni++)
#pragma unroll
            for (int q = 0; q < 4; q++) acc[mi][ni][q] = 0.0f;

    // fragment base byte-offsets within a region
    const uint32_t a_off0 = (uint32_t)(warp_m * 32 + lq) * RB + (uint32_t)lr * 4u;
    const uint32_t b_off0 = (uint32_t)(warp_n * 64 + lq) * RB + (uint32_t)lr * 4u;

#define LOAD_STAGE(buf, kc) do {                                               \
    uint32_t st = sbase + (uint32_t)(buf) * STAGEB;                            \
    const __half* ga_h = ga + (kc) + pch;                                      \
    const __half* gb_h = gb + (kc) + pch;                                      \
    CP16(st + 0 * REGION + prowoff, ga_h);                                     \
    CP16(st + 1 * REGION + prowoff, ga_h + KT);                                \
    CP16(st + 2 * REGION + prowoff, gb_h);                                     \
    CP16(st + 3 * REGION + prowoff, gb_h + KT);                                \
    } while (0)

    // prologue: stages 0..2 committed (3 groups outstanding)
    LOAD_STAGE(0, 0);  CP_COMMIT();
    LOAD_STAGE(1, 16); CP_COMMIT();
    LOAD_STAGE(2, 32); CP_COMMIT();

    for (int k = 0; k < NSTG; k++) {
        CP_WAIT2();                 // stage k resident (<=2 groups outstanding)
        __syncthreads();            // everyone done with stage k-1 buffer

        // prefetch stage k+3 into buffer (k+3)&3 == (k-1)&3 (free post-barrier)
        if (k + 3 < NSTG) LOAD_STAGE((k + 3) & 3, (k + 3) * BK_T);
        CP_COMMIT();                // always commit (empty ok) to keep count

        const uint32_t st = sbase + (uint32_t)(k & 3) * STAGEB;
        const uint32_t sa_h = st + 0 * REGION + a_off0;
        const uint32_t sa_l = st + 1 * REGION + a_off0;
        const uint32_t sb_h = st + 2 * REGION + b_off0;
        const uint32_t sb_l = st + 3 * REGION + b_off0;

        // ---- preload all fragments (48 LDS32) ----
        // A frag regs: a0=[lq][2lr,2lr+1], a1=[lq+8][..], a2=[lq][2lr+8..], a3=[lq+8][2lr+8..]
        uint32_t ah[2][4], al[2][4], bh[8][2], bl[8][2];
#pragma unroll
        for (int mi = 0; mi < 2; mi++) {
            uint32_t base = (uint32_t)mi * (16u * RB);
            LDS32(ah[mi][0], sa_h + base);
            LDS32(ah[mi][1], sa_h + base + 8u * RB);
            LDS32(ah[mi][2], sa_h + base + 16u);
            LDS32(ah[mi][3], sa_h + base + 8u * RB + 16u);
            LDS32(al[mi][0], sa_l + base);
            LDS32(al[mi][1], sa_l + base + 8u * RB);
            LDS32(al[mi][2], sa_l + base + 16u);
            LDS32(al[mi][3], sa_l + base + 8u * RB + 16u);
        }
        // B frag regs: b0=[n=lq][2lr,2lr+1], b1=[n=lq][2lr+8,2lr+9]
#pragma unroll
        for (int ni = 0; ni < 8; ni++) {
            uint32_t base = (uint32_t)ni * (8u * RB);
            LDS32(bh[ni][0], sb_h + base);
            LDS32(bh[ni][1], sb_h + base + 16u);
            LDS32(bl[ni][0], sb_l + base);
            LDS32(bl[ni][1], sb_l + base + 16u);
        }

        // ---- 48 MMAs: term-outer; per-acc order hh -> hl -> lh ----
#pragma unroll
        for (int mi = 0; mi < 2; mi++)
#pragma unroll
            for (int ni = 0; ni < 8; ni++)
                MMA_F16(acc[mi][ni], ah[mi], bh[ni]);   // hi*hi
#pragma unroll
        for (int mi = 0; mi < 2; mi++)
#pragma unroll
            for (int ni = 0; ni < 8; ni++)
                MMA_F16(acc[mi][ni], ah[mi], bl[ni]);   // hi*lo
#pragma unroll
        for (int mi = 0; mi < 2; mi++)
#pragma unroll
            for (int ni = 0; ni < 8; ni++)
                MMA_F16(acc[mi][ni], al[mi], bh[ni]);   // lo*hi
    }

    // epilogue: write C (D fragment: c0=[lq][2lr], c1=[lq][2lr+1],
    //                    c2=[lq+8][2lr], c3=[lq+8][2lr+1])
#pragma unroll
    for (int mi = 0; mi < 2; mi++) {
        const int gm = m0 + warp_m * 32 + mi * 16 + lq;
        float* r0 = g_cur + (size_t)gm * H_SZ + n0 + warp_n * 64 + lr * 2;
        float* r1 = r0 + 8 * H_SZ;
#pragma unroll
        for (int ni = 0; ni < 8; ni++) {
            *(float2*)(r0 + ni * 8) = make_float2(acc[mi][ni][0], acc[mi][ni][1]);
            *(float2*)(r1 + ni * 8) = make_float2(acc[mi][ni][2], acc[mi][ni][3]);
        }
    }
#undef LOAD_STAGE
}

// ---------------------------------------------------------------------------
// LIF scan: S = sum_t c_t * z_t   (per-neuron, state in registers)
// ---------------------------------------------------------------------------
__global__ __launch_bounds__(256)
void scan_kernel() {
    const int gid = blockIdx.x * blockDim.x + threadIdx.x;
    const float4* cur4 = (const float4*)g_cur;

    float v0 = 0.f, v1 = 0.f, v2 = 0.f, v3 = 0.f;
    float i0 = 0.f, i1 = 0.f, i2 = 0.f, i3 = 0.f;
    float s0 = 0.f, s1 = 0.f, s2 = 0.f, s3 = 0.f;

#pragma unroll 4
    for (int t = 0; t < T_STEPS; t++) {
        float4 c = __ldg(&cur4[(size_t)t * (BH / 4) + gid]);
        float coef = g_coef[t];
        float vd, id;
        vd = v0 + 0.1f * ((0.0f - v0) + i0); id = 0.8f * i0;
        if ((vd - 0.25f) > 0.0f) { v0 = 0.0f; s0 += coef; } else { v0 = vd; }
        i0 = id + c.x;
        vd = v1 + 0.1f * ((0.0f - v1) + i1); id = 0.8f * i1;
        if ((vd - 0.25f) > 0.0f) { v1 = 0.0f; s1 += coef; } else { v1 = vd; }
        i1 = id + c.y;
        vd = v2 + 0.1f * ((0.0f - v2) + i2); id = 0.8f * i2;
        if ((vd - 0.25f) > 0.0f) { v2 = 0.0f; s2 += coef; } else { v2 = vd; }
        i2 = id + c.z;
        vd = v3 + 0.1f * ((0.0f - v3) + i3); id = 0.8f * i3;
        if ((vd - 0.25f) > 0.0f) { v3 = 0.0f; s3 += coef; } else { v3 = vd; }
        i3 = id + c.w;
    }
    ((float4*)g_S)[gid] = make_float4(s0, s1, s2, s3);
}

// ---------------------------------------------------------------------------
// Readout: vo = S @ Wout^T
// ---------------------------------------------------------------------------
__global__ __launch_bounds__(256)
void readout_kernel(const float* __restrict__ Wout, float* __restrict__ out) {
    const int b = blockIdx.x;
    const int tid = threadIdx.x;
    float acc[OUT_SZ];
#pragma unroll
    for (int o = 0; o < OUT_SZ; o++) acc[o] = 0.0f;

    const float* srow = g_S + (size_t)b * H_SZ;
    for (int h = tid; h < H_SZ; h += 256) {
        float sv = srow[h];
#pragma unroll
        for (int o = 0; o < OUT_SZ; o++)
            acc[o] = fmaf(sv, __ldg(&Wout[o * H_SZ + h]), acc[o]);
    }
    __shared__ float red[OUT_SZ][8];
    const int lane = tid & 31, warp = tid >> 5;
#pragma unroll
    for (int o = 0; o < OUT_SZ; o++) {
        float v = acc[o];
#pragma unroll
        for (int off = 16; off; off >>= 1) v += __shfl_down_sync(0xffffffffu, v, off);
        if (lane == 0) red[o][warp] = v;
    }
    __syncthreads();
    if (tid < OUT_SZ) {
        float v = 0.0f;
#pragma unroll
        for (int w = 0; w < 8; w++) v += red[tid][w];
        out[b * OUT_SZ + tid] = v;
    }
}

// ---------------------------------------------------------------------------
extern "C" void kernel_launch(void* const* d_in, const int* in_sizes, int n_in,
                              void* d_out, int out_size) {
    const float* x    = (const float*)d_in[0];   // [128,512,784]
    const float* W1   = (const float*)d_in[1];   // [2048,784]
    const float* Wout = (const float*)d_in[2];   // [10,2048]
    float* out = (float*)d_out;                  // [512,10]

    coef_kernel<<<1, 128>>>();
    packA_kernel<<<MB, 256>>>(x);
    packB_kernel<<<H_SZ, 256>>>(W1);

    cudaFuncSetAttribute(mma_kernel, cudaFuncAttributeMaxDynamicSharedMemorySize, SMEMB);
    dim3 grid(H_SZ / BN_T, MB / BM_T);   // (16, 512), x fastest
    mma_kernel<<<grid, 256, SMEMB>>>();

    scan_kernel<<<BH / 4 / 256, 256>>>();
    readout_kernel<<<B_SZ, 256>>>(Wout, out);
}

// round 8
// speedup vs baseline: 1.7859x; 1.3430x over previous
#include <cuda_runtime.h>
#include <cuda_fp16.h>
#include <cstdint>
#include <math.h>

// ---------------------------------------------------------------------------
// Problem dims
// ---------------------------------------------------------------------------
#define T_STEPS 128
#define B_SZ    512
#define IN_SZ   784
#define H_SZ    2048
#define OUT_SZ  10
#define MB      (T_STEPS * B_SZ)          // 65536 GEMM rows
#define BH      (B_SZ * H_SZ)             // 1048576 neurons

#define KT      784                       // K elements
#define KAP     1568                      // packed row stride in halfs: [hi|lo]

// GEMM tiling: 128x128 CTA, 4 warps (2x2) of 64x64 warp tiles
#define BM_T    128
#define BN_T    128
#define BK_T    16                        // K per stage = one m16n8k16 MMA
#define NSTG    49                        // 784 / 16
#define RB      48                        // smem row bytes (32B data + 16B pad)
#define REGION  (128 * RB)                // 6144 B: one of {Ahi,Alo,Bhi,Blo}
#define STAGEB  (4 * REGION)              // 24576 B per stage
#define SMEMB   (4 * STAGEB)              // 98304 B total (4 stages)

// Scratch (device globals — no runtime allocation allowed)
__device__ float  g_cur[(size_t)MB * H_SZ];    // 512 MB
__device__ __half g_A[(size_t)MB * KAP];       // 205 MB packed [hi|lo] X (fp16)
__device__ __half g_B[(size_t)H_SZ * KAP];     // 6.4 MB packed [hi|lo] W1
__device__ float  g_S[(size_t)B_SZ * H_SZ];    // weighted spike sums
__device__ float  g_coef[T_STEPS];

// ---------------------------------------------------------------------------
// PTX helpers (arch-agnostic only: cp.async + mma.sync)
// ---------------------------------------------------------------------------
__device__ __forceinline__ uint32_t smem_u32(const void* p) {
    uint32_t a;
    asm("{ .reg .u64 t; cvta.to.shared.u64 t, %1; cvt.u32.u64 %0, t; }"
        : "=r"(a) : "l"(p));
    return a;
}
#define CP16(dst, src) \
    asm volatile("cp.async.cg.shared.global [%0], [%1], 16;" :: "r"(dst), "l"(src) : "memory")
#define CP_COMMIT() asm volatile("cp.async.commit_group;" ::: "memory")
#define CP_WAIT2()  asm volatile("cp.async.wait_group 2;" ::: "memory")

#define LDS32(reg, addr) \
    asm volatile("ld.shared.b32 %0, [%1];" : "=r"(reg) : "r"(addr))

// D += A*B  (m16n8k16, fp16 inputs packed f16x2 in b32 regs, fp32 accumulate)
#define MMA_F16(c, a, b)                                                       \
    asm volatile(                                                              \
        "mma.sync.aligned.m16n8k16.row.col.f32.f16.f16.f32 "                   \
        "{%0,%1,%2,%3}, {%4,%5,%6,%7}, {%8,%9}, {%0,%1,%2,%3};"                \
        : "+f"((c)[0]), "+f"((c)[1]), "+f"((c)[2]), "+f"((c)[3])               \
        : "r"((a)[0]), "r"((a)[1]), "r"((a)[2]), "r"((a)[3]),                  \
          "r"((b)[0]), "r"((b)[1]))

// ---------------------------------------------------------------------------
// Kernel 0: readout coefficients  c_t = 0.9^(127-t) - 0.8^(127-t)
// ---------------------------------------------------------------------------
__global__ void coef_kernel() {
    int t = threadIdx.x;
    if (t < T_STEPS) {
        float m = (float)(T_STEPS - 1 - t);
        g_coef[t] = powf(0.9f, m) - powf(0.8f, m);
    }
}

// ---------------------------------------------------------------------------
// Pack kernels: split fp32 -> (hi, lo) fp16 pairs (11-bit limbs)
// ---------------------------------------------------------------------------
__global__ __launch_bounds__(256)
void packA_kernel(const float* __restrict__ x) {
    size_t m = blockIdx.x;
    const float* src = x + m * IN_SZ;
    __half* dst = g_A + m * KAP;
    for (int k = threadIdx.x; k < KT; k += 256) {
        float v = src[k];
        __half h = __float2half_rn(v);
        dst[k] = h;
        dst[KT + k] = __float2half_rn(v - __half2float(h));
    }
}
__global__ __launch_bounds__(256)
void packB_kernel(const float* __restrict__ w) {
    size_t n = blockIdx.x;
    const float* src = w + n * IN_SZ;
    __half* dst = g_B + n * KAP;
    for (int k = threadIdx.x; k < KT; k += 256) {
        float v = src[k];
        __half h = __float2half_rn(v);
        dst[k] = h;
        dst[KT + k] = __float2half_rn(v - __half2float(h));
    }
}

// ---------------------------------------------------------------------------
// GEMM: CUR[65536,2048] = X @ W1^T, fp16x3 emulation on mma.sync m16n8k16.
// 128x128 CTA tile, 4 warps (2x2) of 64x64 warp tiles, BK=16, 4-stage cp.async.
// Per warp-stage: 64 LDS32 + 96 HMMA (32 accs x {hh, hl, lh}) -> MMA:LDS = 1.5
// (was 1.0), cutting smem-crossbar pressure ~33% per MAC. 2 CTAs/SM retained.
// Accumulation order per output element unchanged -> bit-identical results.
// ---------------------------------------------------------------------------
__global__ __launch_bounds__(128, 2)
void mma_kernel() {
    extern __shared__ __align__(16) char smem[];
    const uint32_t sbase = smem_u32(smem);

    const int tid  = threadIdx.x;
    const int wid  = tid >> 5;
    const int lane = tid & 31;
    const int lq   = lane >> 2;           // 0..7  (group)
    const int lr   = lane & 3;            // 0..3  (thread-in-group)
    const int warp_m = wid & 1;           // 2 strips of 64 rows
    const int warp_n = wid >> 1;          // 2 strips of 64 cols

    const int n0 = blockIdx.x * BN_T;     // x fastest -> A-tile L2 reuse
    const int m0 = blockIdx.y * BM_T;

    // ---- producer mapping: thread t owns row t of all 4 regions ----
    // per stage: 8 x CP16 per thread (2 per region: halves 0-7 and 8-15)
    const int prow = tid;                 // 0..127
    const __half* ga = g_A + (size_t)(m0 + prow) * KAP;
    const __half* gb = g_B + (size_t)(n0 + prow) * KAP;
    const uint32_t prowoff = (uint32_t)prow * RB;

    float acc[4][8][4];
#pragma unroll
    for (int mi = 0; mi < 4; mi++)
#pragma unroll
        for (int ni = 0; ni < 8; ni++)
#pragma unroll
            for (int q = 0; q < 4; q++) acc[mi][ni][q] = 0.0f;

    // fragment base byte-offsets within a region
    const uint32_t a_off0 = (uint32_t)(warp_m * 64 + lq) * RB + (uint32_t)lr * 4u;
    const uint32_t b_off0 = (uint32_t)(warp_n * 64 + lq) * RB + (uint32_t)lr * 4u;

#define LOAD_STAGE(buf, kc) do {                                               \
    uint32_t st = sbase + (uint32_t)(buf) * STAGEB;                            \
    const __half* ga_h = ga + (kc);                                            \
    const __half* gb_h = gb + (kc);                                            \
    CP16(st + 0 * REGION + prowoff,       ga_h);                               \
    CP16(st + 0 * REGION + prowoff + 16u, ga_h + 8);                           \
    CP16(st + 1 * REGION + prowoff,       ga_h + KT);                          \
    CP16(st + 1 * REGION + prowoff + 16u, ga_h + KT + 8);                      \
    CP16(st + 2 * REGION + prowoff,       gb_h);                               \
    CP16(st + 2 * REGION + prowoff + 16u, gb_h + 8);                           \
    CP16(st + 3 * REGION + prowoff,       gb_h + KT);                          \
    CP16(st + 3 * REGION + prowoff + 16u, gb_h + KT + 8);                      \
    } while (0)

    // prologue: stages 0..2 committed (3 groups outstanding)
    LOAD_STAGE(0, 0);  CP_COMMIT();
    LOAD_STAGE(1, 16); CP_COMMIT();
    LOAD_STAGE(2, 32); CP_COMMIT();

    for (int k = 0; k < NSTG; k++) {
        CP_WAIT2();                 // stage k resident (<=2 groups outstanding)
        __syncthreads();            // everyone done with stage k-1 buffer

        // prefetch stage k+3 into buffer (k+3)&3 == (k-1)&3 (free post-barrier)
        if (k + 3 < NSTG) LOAD_STAGE((k + 3) & 3, (k + 3) * BK_T);
        CP_COMMIT();                // always commit (empty ok) to keep count

        const uint32_t st = sbase + (uint32_t)(k & 3) * STAGEB;
        const uint32_t sa_h = st + 0 * REGION + a_off0;
        const uint32_t sa_l = st + 1 * REGION + a_off0;
        const uint32_t sb_h = st + 2 * REGION + b_off0;
        const uint32_t sb_l = st + 3 * REGION + b_off0;

        // ---- preload all fragments (64 LDS32) ----
        uint32_t ah[4][4], al[4][4], bh[8][2], bl[8][2];
#pragma unroll
        for (int mi = 0; mi < 4; mi++) {
            uint32_t base = (uint32_t)mi * (16u * RB);
            LDS32(ah[mi][0], sa_h + base);
            LDS32(ah[mi][1], sa_h + base + 8u * RB);
            LDS32(ah[mi][2], sa_h + base + 16u);
            LDS32(ah[mi][3], sa_h + base + 8u * RB + 16u);
            LDS32(al[mi][0], sa_l + base);
            LDS32(al[mi][1], sa_l + base + 8u * RB);
            LDS32(al[mi][2], sa_l + base + 16u);
            LDS32(al[mi][3], sa_l + base + 8u * RB + 16u);
        }
#pragma unroll
        for (int ni = 0; ni < 8; ni++) {
            uint32_t base = (uint32_t)ni * (8u * RB);
            LDS32(bh[ni][0], sb_h + base);
            LDS32(bh[ni][1], sb_h + base + 16u);
            LDS32(bl[ni][0], sb_l + base);
            LDS32(bl[ni][1], sb_l + base + 16u);
        }

        // ---- 96 MMAs: term-outer; per-acc order hh -> hl -> lh ----
#pragma unroll
        for (int mi = 0; mi < 4; mi++)
#pragma unroll
            for (int ni = 0; ni < 8; ni++)
                MMA_F16(acc[mi][ni], ah[mi], bh[ni]);   // hi*hi
#pragma unroll
        for (int mi = 0; mi < 4; mi++)
#pragma unroll
            for (int ni = 0; ni < 8; ni++)
                MMA_F16(acc[mi][ni], ah[mi], bl[ni]);   // hi*lo
#pragma unroll
        for (int mi = 0; mi < 4; mi++)
#pragma unroll
            for (int ni = 0; ni < 8; ni++)
                MMA_F16(acc[mi][ni], al[mi], bh[ni]);   // lo*hi
    }

    // epilogue: write C (D frag: c0=[lq][2lr], c1=[lq][2lr+1],
    //                    c2=[lq+8][2lr], c3=[lq+8][2lr+1])
#pragma unroll
    for (int mi = 0; mi < 4; mi++) {
        const int gm = m0 + warp_m * 64 + mi * 16 + lq;
        float* r0 = g_cur + (size_t)gm * H_SZ + n0 + warp_n * 64 + lr * 2;
        float* r1 = r0 + 8 * H_SZ;
#pragma unroll
        for (int ni = 0; ni < 8; ni++) {
            *(float2*)(r0 + ni * 8) = make_float2(acc[mi][ni][0], acc[mi][ni][1]);
            *(float2*)(r1 + ni * 8) = make_float2(acc[mi][ni][2], acc[mi][ni][3]);
        }
    }
#undef LOAD_STAGE
}

// ---------------------------------------------------------------------------
// LIF scan: S = sum_t c_t * z_t   (per-neuron, state in registers)
// ---------------------------------------------------------------------------
__global__ __launch_bounds__(256)
void scan_kernel() {
    const int gid = blockIdx.x * blockDim.x + threadIdx.x;
    const float4* cur4 = (const float4*)g_cur;

    float v0 = 0.f, v1 = 0.f, v2 = 0.f, v3 = 0.f;
    float i0 = 0.f, i1 = 0.f, i2 = 0.f, i3 = 0.f;
    float s0 = 0.f, s1 = 0.f, s2 = 0.f, s3 = 0.f;

#pragma unroll 4
    for (int t = 0; t < T_STEPS; t++) {
        float4 c = __ldg(&cur4[(size_t)t * (BH / 4) + gid]);
        float coef = g_coef[t];
        float vd, id;
        vd = v0 + 0.1f * ((0.0f - v0) + i0); id = 0.8f * i0;
        if ((vd - 0.25f) > 0.0f) { v0 = 0.0f; s0 += coef; } else { v0 = vd; }
        i0 = id + c.x;
        vd = v1 + 0.1f * ((0.0f - v1) + i1); id = 0.8f * i1;
        if ((vd - 0.25f) > 0.0f) { v1 = 0.0f; s1 += coef; } else { v1 = vd; }
        i1 = id + c.y;
        vd = v2 + 0.1f * ((0.0f - v2) + i2); id = 0.8f * i2;
        if ((vd - 0.25f) > 0.0f) { v2 = 0.0f; s2 += coef; } else { v2 = vd; }
        i2 = id + c.z;
        vd = v3 + 0.1f * ((0.0f - v3) + i3); id = 0.8f * i3;
        if ((vd - 0.25f) > 0.0f) { v3 = 0.0f; s3 += coef; } else { v3 = vd; }
        i3 = id + c.w;
    }
    ((float4*)g_S)[gid] = make_float4(s0, s1, s2, s3);
}

// ---------------------------------------------------------------------------
// Readout: vo = S @ Wout^T
// ---------------------------------------------------------------------------
__global__ __launch_bounds__(256)
void readout_kernel(const float* __restrict__ Wout, float* __restrict__ out) {
    const int b = blockIdx.x;
    const int tid = threadIdx.x;
    float acc[OUT_SZ];
#pragma unroll
    for (int o = 0; o < OUT_SZ; o++) acc[o] = 0.0f;

    const float* srow = g_S + (size_t)b * H_SZ;
    for (int h = tid; h < H_SZ; h += 256) {
        float sv = srow[h];
#pragma unroll
        for (int o = 0; o < OUT_SZ; o++)
            acc[o] = fmaf(sv, __ldg(&Wout[o * H_SZ + h]), acc[o]);
    }
    __shared__ float red[OUT_SZ][8];
    const int lane = tid & 31, warp = tid >> 5;
#pragma unroll
    for (int o = 0; o < OUT_SZ; o++) {
        float v = acc[o];
#pragma unroll
        for (int off = 16; off; off >>= 1) v += __shfl_down_sync(0xffffffffu, v, off);
        if (lane == 0) red[o][warp] = v;
    }
    __syncthreads();
    if (tid < OUT_SZ) {
        float v = 0.0f;
#pragma unroll
        for (int w = 0; w < 8; w++) v += red[tid][w];
        out[b * OUT_SZ + tid] = v;
    }
}

// ---------------------------------------------------------------------------
extern "C" void kernel_launch(void* const* d_in, const int* in_sizes, int n_in,
                              void* d_out, int out_size) {
    const float* x    = (const float*)d_in[0];   // [128,512,784]
    const float* W1   = (const float*)d_in[1];   // [2048,784]
    const float* Wout = (const float*)d_in[2];   // [10,2048]
    float* out = (float*)d_out;                  // [512,10]

    coef_kernel<<<1, 128>>>();
    packA_kernel<<<MB, 256>>>(x);
    packB_kernel<<<H_SZ, 256>>>(W1);

    cudaFuncSetAttribute(mma_kernel, cudaFuncAttributeMaxDynamicSharedMemorySize, SMEMB);
    dim3 grid(H_SZ / BN_T, MB / BM_T);   // (16, 512), x fastest
    mma_kernel<<<grid, 128, SMEMB>>>();

    scan_kernel<<<BH / 4 / 256, 256>>>();
    readout_kernel<<<B_SZ, 256>>>(Wout, out);
}